// round 13
// baseline (speedup 1.0000x reference)
#include <cuda_runtime.h>
#include <cuda_bf16.h>
#include <cstdint>

// Problem dims
#define BB 64
#define TT 128
#define SS 128
#define CC 512
#define HH 8
#define DHH 64
#define FFF 2048
#define LL 6
#define LN_EPS 1e-5f

typedef unsigned long long ull;
typedef __nv_bfloat16 bf16;

// ---------------- scratch (static device allocations — allowed) --------------
__device__ float g_x[BB * TT * CC];
__device__ float g_q[BB * HH * TT * DHH];
__device__ float g_k[BB * HH * TT * DHH];
__device__ float g_v[BB * HH * TT * DHH];
__device__ float g_att[BB * TT * CC];
__device__ bf16 g_xhi[BB * TT * CC];          // split activations (decoder x)
__device__ bf16 g_xlo[BB * TT * CC];
__device__ bf16 g_ehi[BB * SS * CC];          // split encoder output
__device__ bf16 g_elo[BB * SS * CC];
__device__ bf16 g_hhi[BB * TT * FFF];         // split ff hidden
__device__ bf16 g_hlo[BB * TT * FFF];
__device__ bf16 g_whi[2048 * 512];            // prepped weights (max N*K = 1M)
__device__ bf16 g_wlo[2048 * 512];
__device__ float g_bias[2048];
__device__ float g_red[BB * 8 * 2];           // LN partial sums

// ---------------- packed f32x2 helpers ---------------------------------------
__device__ __forceinline__ ull ffma2(ull a, ull b, ull c) {
    ull d; asm("fma.rn.f32x2 %0, %1, %2, %3;" : "=l"(d) : "l"(a), "l"(b), "l"(c));
    return d;
}
__device__ __forceinline__ ull splat2(float x) {
    ull d; asm("mov.b64 %0, {%1, %1};" : "=l"(d) : "f"(x)); return d;
}
__device__ __forceinline__ float2 unpack2(ull v) {
    float2 r; asm("mov.b64 {%0, %1}, %2;" : "=f"(r.x), "=f"(r.y) : "l"(v)); return r;
}
__device__ __forceinline__ uint32_t smem_u32(const void* p) {
    uint32_t a;
    asm("{ .reg .u64 t; cvta.to.shared.u64 t, %1; cvt.u32.u64 %0, t; }" : "=r"(a) : "l"(p));
    return a;
}
__device__ __forceinline__ uint32_t bfu(bf16 v) {
    return (uint32_t)__bfloat16_as_ushort(v);
}
// split one fp32 -> hi/lo bf16 pair
__device__ __forceinline__ void split1(float x, uint32_t& hi, uint32_t& lo) {
    bf16 h = __float2bfloat16_rn(x);
    hi = bfu(h);
    lo = bfu(__float2bfloat16_rn(x - __bfloat162float(h)));
}

// ---------------- mma.sync / ldmatrix / cp.async (plain-sm_103 PTX) ----------
#define LDX4(r0, r1, r2, r3, addr) \
    asm volatile("ldmatrix.sync.aligned.m8n8.x4.shared.b16 {%0,%1,%2,%3}, [%4];" \
                 : "=r"(r0), "=r"(r1), "=r"(r2), "=r"(r3) : "r"(addr))

__device__ __forceinline__ void mma16816(float* c, const uint32_t* a, const uint32_t* b) {
    asm volatile(
        "mma.sync.aligned.m16n8k16.row.col.f32.bf16.bf16.f32 "
        "{%0,%1,%2,%3}, {%4,%5,%6,%7}, {%8,%9}, {%0,%1,%2,%3};"
        : "+f"(c[0]), "+f"(c[1]), "+f"(c[2]), "+f"(c[3])
        : "r"(a[0]), "r"(a[1]), "r"(a[2]), "r"(a[3]), "r"(b[0]), "r"(b[1]));
}
__device__ __forceinline__ void cpasync16(uint32_t dst, const void* src) {
    asm volatile("cp.async.cg.shared.global [%0], [%1], 16;" :: "r"(dst), "l"(src));
}

// =============================================================================
// HMMA split-bf16 GEMM, cp.async 3-stage pipelined, 2 CTAs/SM.
// CTA tile 128x128, BK=32, 8 warps (2x4), warp tile 64x32, 3-term compensation.
// smem rows PACK hi+lo: [32 hi halves | 32 lo halves | 16B pad] = 144B stride
// (16B-aligned; 8 rows*144 mod 128 = {0,16,..,112} all distinct banks).
// Stage = A-pack + B-pack = 2*18432 = 36864B; 3 stages = 110592B -> 2 CTAs/SM.
// ONE __syncthreads per K-chunk; loads run 2 chunks ahead.
// mode: 0 = fp32 out (+res,+relu)   1 = qkv scatter   2 = bf16 hi/lo out (+relu)
// =============================================================================
#define AR_STRIDE 144
#define MAT_BYTES (128 * AR_STRIDE)           // 18432 (one packed matrix)
#define STAGE_BYTES (2 * MAT_BYTES)           // 36864
#define GEMM_SMEM (3 * STAGE_BYTES)           // 110592 -> 2 CTAs/SM

__global__ __launch_bounds__(256, 2) void gemm_mma(
    const bf16* __restrict__ Aq_hi, const bf16* __restrict__ Aq_lo,
    const bf16* __restrict__ Akv_hi, const bf16* __restrict__ Akv_lo, int Kdim,
    const bf16* __restrict__ Whi, const bf16* __restrict__ Wlo,
    const float* __restrict__ bias, const float* __restrict__ res,
    float* __restrict__ outp, bf16* __restrict__ ohi, bf16* __restrict__ olo, int ldo,
    float* __restrict__ Oq, float* __restrict__ Ok, float* __restrict__ Ov,
    int relu, int mode)
{
    extern __shared__ char sm[];
    const uint32_t smb = smem_u32(sm);
    const int tid = threadIdx.x;
    const int wid = tid >> 5, lane = tid & 31;
    const int mw = wid >> 2, nw = wid & 3;

    const int m0 = blockIdx.x * 128;
    const int n0 = blockIdx.y * 128;
    const bf16 *Ahp, *Alp;
    if (mode == 1 && n0 >= 512) { Ahp = Akv_hi; Alp = Akv_lo; }
    else                        { Ahp = Aq_hi;  Alp = Aq_lo; }

    // per-thread load slots: lr = tid>>1 (row 0..127), lh = tid&1 (0=hi, 1=lo)
    // each thread copies 4x16B (64B) of its row-half for A and for B.
    const int lr = tid >> 1, lh = tid & 1;
    const bf16* pA = (lh ? Alp : Ahp) + (size_t)(m0 + lr) * Kdim;
    const bf16* pB = (lh ? Wlo : Whi) + (size_t)(n0 + lr) * Kdim;
    const uint32_t soRow = lr * AR_STRIDE + lh * 64;

    float acc[4][4][4];
#pragma unroll
    for (int i = 0; i < 4; i++)
#pragma unroll
        for (int j = 0; j < 4; j++)
#pragma unroll
            for (int r = 0; r < 4; r++) acc[i][j][r] = 0.f;

    // ldmatrix per-lane offsets (relative to stage base); hi at +0, lo at +64
    const int aoff = (mw * 64 + (lane & 15)) * AR_STRIDE + (lane >> 4) * 16;
    const int mi = lane >> 3;
    const int n_off = ((mi >> 1) * 8) + (lane & 7);
    const int k_off = (mi & 1) * 8;
    const int boff = (nw * 32 + n_off) * AR_STRIDE + k_off * 2;

    const int nch = Kdim >> 5;

#define LOAD_STAGE(slotb, kc) do {                                             \
        _Pragma("unroll")                                                      \
        for (int j = 0; j < 4; j++) {                                          \
            cpasync16((slotb) + soRow + j * 16,             pA + (kc) + j * 8);\
            cpasync16((slotb) + MAT_BYTES + soRow + j * 16, pB + (kc) + j * 8);\
        }                                                                      \
        asm volatile("cp.async.commit_group;");                                \
    } while (0)

    LOAD_STAGE(smb, 0);
    LOAD_STAGE(smb + STAGE_BYTES, 32);

    int cs = 0, ls = 2;
    for (int c = 0; c < nch; c++) {
        if (c + 1 < nch) asm volatile("cp.async.wait_group 1;");
        else             asm volatile("cp.async.wait_group 0;");
        __syncthreads();
        if (c + 2 < nch) {
            LOAD_STAGE(smb + ls * STAGE_BYTES, (c + 2) << 5);
            ls = (ls == 2) ? 0 : ls + 1;
        }

        const uint32_t sb = smb + cs * STAGE_BYTES;
        cs = (cs == 2) ? 0 : cs + 1;
        const uint32_t sA = sb, sB = sb + MAT_BYTES;

#pragma unroll
        for (int kk = 0; kk < 2; kk++) {
            uint32_t bh[4][2], bl[4][2];
            LDX4(bh[0][0], bh[0][1], bh[1][0], bh[1][1], sB + boff + kk * 32);
            LDX4(bh[2][0], bh[2][1], bh[3][0], bh[3][1], sB + boff + 16 * AR_STRIDE + kk * 32);
            LDX4(bl[0][0], bl[0][1], bl[1][0], bl[1][1], sB + boff + 64 + kk * 32);
            LDX4(bl[2][0], bl[2][1], bl[3][0], bl[3][1], sB + boff + 16 * AR_STRIDE + 64 + kk * 32);
#pragma unroll
            for (int i = 0; i < 4; i++) {
                uint32_t ah[4], al[4];
                LDX4(ah[0], ah[1], ah[2], ah[3], sA + aoff + i * 16 * AR_STRIDE + kk * 32);
                LDX4(al[0], al[1], al[2], al[3], sA + aoff + i * 16 * AR_STRIDE + 64 + kk * 32);
#pragma unroll
                for (int j = 0; j < 4; j++) {
                    mma16816(acc[i][j], ah, bh[j]);
                    mma16816(acc[i][j], ah, bl[j]);
                    mma16816(acc[i][j], al, bh[j]);
                }
            }
        }
    }
#undef LOAD_STAGE

    // ---- epilogue ----
    const int gid = lane >> 2, tg = lane & 3;
#pragma unroll
    for (int i = 0; i < 4; i++) {
#pragma unroll
        for (int j = 0; j < 4; j++) {
            int row0 = m0 + mw * 64 + i * 16 + gid;
            int row1 = row0 + 8;
            int col = n0 + nw * 32 + j * 8 + tg * 2;
            float b0v = bias[col], b1v = bias[col + 1];
            float v00 = acc[i][j][0] + b0v, v01 = acc[i][j][1] + b1v;
            float v10 = acc[i][j][2] + b0v, v11 = acc[i][j][3] + b1v;
            if (mode == 0) {
                if (res) {
                    float2 r0 = *(const float2*)(res + (size_t)row0 * ldo + col);
                    float2 r1 = *(const float2*)(res + (size_t)row1 * ldo + col);
                    v00 += r0.x; v01 += r0.y; v10 += r1.x; v11 += r1.y;
                }
                if (relu) {
                    v00 = fmaxf(v00, 0.f); v01 = fmaxf(v01, 0.f);
                    v10 = fmaxf(v10, 0.f); v11 = fmaxf(v11, 0.f);
                }
                *(float2*)(outp + (size_t)row0 * ldo + col) = make_float2(v00, v01);
                *(float2*)(outp + (size_t)row1 * ldo + col) = make_float2(v10, v11);
            } else if (mode == 1) {
                const int z = col >> 9, hh = (col >> 6) & 7, d0 = col & 63;
                float* O = (z == 0) ? Oq : (z == 1 ? Ok : Ov);
                int b0i = row0 >> 7, t0 = row0 & 127;
                int b1i = row1 >> 7, t1 = row1 & 127;
                *(float2*)(O + (((size_t)(b0i * HH + hh)) * TT + t0) * DHH + d0) = make_float2(v00, v01);
                *(float2*)(O + (((size_t)(b1i * HH + hh)) * TT + t1) * DHH + d0) = make_float2(v10, v11);
            } else {
                if (relu) {
                    v00 = fmaxf(v00, 0.f); v01 = fmaxf(v01, 0.f);
                    v10 = fmaxf(v10, 0.f); v11 = fmaxf(v11, 0.f);
                }
                uint32_t h00, l00, h01, l01, h10, l10, h11, l11;
                split1(v00, h00, l00); split1(v01, h01, l01);
                split1(v10, h10, l10); split1(v11, h11, l11);
                *(uint32_t*)(ohi + (size_t)row0 * ldo + col) = h00 | (h01 << 16);
                *(uint32_t*)(olo + (size_t)row0 * ldo + col) = l00 | (l01 << 16);
                *(uint32_t*)(ohi + (size_t)row1 * ldo + col) = h10 | (h11 << 16);
                *(uint32_t*)(olo + (size_t)row1 * ldo + col) = l10 | (l11 << 16);
            }
        }
    }
}

// =============================================================================
// Weight prep: transpose fp32 weights into K-major bf16 hi/lo [N,K]
// =============================================================================
__global__ __launch_bounds__(256) void prep_qkv(
    const float* __restrict__ wq, const float* __restrict__ wk, const float* __restrict__ wv,
    const float* __restrict__ bq, const float* __restrict__ bk, const float* __restrict__ bv,
    bf16* __restrict__ whi, bf16* __restrict__ wlo, float* __restrict__ gb)
{
    __shared__ float smt[64][65];
    const int tid = threadIdx.x;
    const int c0 = blockIdx.x * 64;
    const int nb0 = blockIdx.y * 64;
    const int z = nb0 >> 9, hh = (nb0 >> 6) & 7;
    const float* W = ((z == 0) ? wq : (z == 1 ? wk : wv)) + (size_t)hh * CC * DHH;

#pragma unroll
    for (int p = 0; p < 4; p++) {
        int v = p * 256 + tid;
        int ci = v >> 4, q = v & 15;
        float4 a = *(const float4*)(W + (size_t)(c0 + ci) * DHH + q * 4);
        smt[ci][q * 4 + 0] = a.x; smt[ci][q * 4 + 1] = a.y;
        smt[ci][q * 4 + 2] = a.z; smt[ci][q * 4 + 3] = a.w;
    }
    __syncthreads();
#pragma unroll
    for (int p = 0; p < 2; p++) {
        int u = p * 256 + tid;
        int d = u >> 3, cv = u & 7;
        uint4 uh, ul;
        uint32_t* ph = (uint32_t*)&uh;
        uint32_t* pl = (uint32_t*)&ul;
#pragma unroll
        for (int j = 0; j < 4; j++) {
            uint32_t h0, l0, h1, l1;
            split1(smt[cv * 8 + 2 * j][d], h0, l0);
            split1(smt[cv * 8 + 2 * j + 1][d], h1, l1);
            ph[j] = h0 | (h1 << 16);
            pl[j] = l0 | (l1 << 16);
        }
        size_t o = (size_t)(nb0 + d) * CC + c0 + cv * 8;
        *(uint4*)(whi + o) = uh;
        *(uint4*)(wlo + o) = ul;
    }
    if (blockIdx.x == 0 && tid < 64) {
        const float* bsrc = (z == 0) ? bq : (z == 1 ? bk : bv);
        gb[nb0 + tid] = bsrc[hh * DHH + tid];
    }
}

__global__ __launch_bounds__(256) void prep_plain(
    const float* __restrict__ W, int Kd, int Nd,
    bf16* __restrict__ whi, bf16* __restrict__ wlo)
{
    __shared__ float smt[64][65];
    const int tid = threadIdx.x;
    const int c0 = blockIdx.x * 64;
    const int nb0 = blockIdx.y * 64;

#pragma unroll
    for (int p = 0; p < 4; p++) {
        int v = p * 256 + tid;
        int ci = v >> 4, q = v & 15;
        float4 a = *(const float4*)(W + (size_t)(c0 + ci) * Nd + nb0 + q * 4);
        smt[ci][q * 4 + 0] = a.x; smt[ci][q * 4 + 1] = a.y;
        smt[ci][q * 4 + 2] = a.z; smt[ci][q * 4 + 3] = a.w;
    }
    __syncthreads();
#pragma unroll
    for (int p = 0; p < 2; p++) {
        int u = p * 256 + tid;
        int d = u >> 3, cv = u & 7;
        uint4 uh, ul;
        uint32_t* ph = (uint32_t*)&uh;
        uint32_t* pl = (uint32_t*)&ul;
#pragma unroll
        for (int j = 0; j < 4; j++) {
            uint32_t h0, l0, h1, l1;
            split1(smt[cv * 8 + 2 * j][d], h0, l0);
            split1(smt[cv * 8 + 2 * j + 1][d], h1, l1);
            ph[j] = h0 | (h1 << 16);
            pl[j] = l0 | (l1 << 16);
        }
        size_t o = (size_t)(nb0 + d) * Kd + c0 + cv * 8;
        *(uint4*)(whi + o) = uh;
        *(uint4*)(wlo + o) = ul;
    }
}

// ---- standalone fp32 -> bf16 hi/lo split (for x_in and encoder_output) ------
__global__ __launch_bounds__(256) void conv_split(
    const float* __restrict__ a, bf16* __restrict__ hi, bf16* __restrict__ lo, int n8)
{
    for (int i = blockIdx.x * 256 + threadIdx.x; i < n8; i += gridDim.x * 256) {
        float4 v0 = *(const float4*)(a + (size_t)i * 8);
        float4 v1 = *(const float4*)(a + (size_t)i * 8 + 4);
        uint4 uh, ul;
        uint32_t* ph = (uint32_t*)&uh;
        uint32_t* pl = (uint32_t*)&ul;
#pragma unroll
        for (int j = 0; j < 4; j++) {
            float x0 = (j < 2) ? ((const float*)&v0)[2 * j] : ((const float*)&v1)[2 * (j - 2)];
            float x1 = (j < 2) ? ((const float*)&v0)[2 * j + 1] : ((const float*)&v1)[2 * (j - 2) + 1];
            uint32_t h0, l0v, h1, l1v;
            split1(x0, h0, l0v); split1(x1, h1, l1v);
            ph[j] = h0 | (h1 << 16);
            pl[j] = l0v | (l1v << 16);
        }
        *(uint4*)(hi + (size_t)i * 8) = uh;
        *(uint4*)(lo + (size_t)i * 8) = ul;
    }
}

// =============================================================================
// Attention: one CTA per (b,h). 128 threads, thread t owns query row t.
// =============================================================================
__global__ __launch_bounds__(128) void attn_kernel(
    const float* __restrict__ Q, const float* __restrict__ K,
    const float* __restrict__ V, float* __restrict__ outp)
{
    extern __shared__ float smf[];
    float* KV = smf;
    float* P = smf + TT * DHH;

    const int bh = blockIdx.x;
    const int t = threadIdx.x;
    const size_t base = (size_t)bh * TT * DHH;
    const float* Qp = Q + base;
    const float* Kp = K + base;
    const float* Vp = V + base;

    for (int i = t * 4; i < TT * DHH; i += 128 * 4)
        *(float4*)&KV[i] = *(const float4*)&Kp[i];

    ulonglong2 q2[16];
    const ulonglong2* qsrc = (const ulonglong2*)(Qp + (size_t)t * DHH);
#pragma unroll
    for (int i = 0; i < 16; i++) q2[i] = qsrc[i];
    __syncthreads();

    float* Prow = P + t * 129;
    float mx = -1e30f;
    for (int s = 0; s < SS; s++) {
        const ulonglong2* kp2 = (const ulonglong2*)(KV + s * DHH);
        ull a0 = 0, a1 = 0, a2v = 0, a3 = 0;
#pragma unroll
        for (int i = 0; i < 16; i += 2) {
            ulonglong2 kv0 = kp2[i], kv1 = kp2[i + 1];
            a0 = ffma2(q2[i].x, kv0.x, a0);
            a1 = ffma2(q2[i].y, kv0.y, a1);
            a2v = ffma2(q2[i + 1].x, kv1.x, a2v);
            a3 = ffma2(q2[i + 1].y, kv1.y, a3);
        }
        float2 f0 = unpack2(a0), f1 = unpack2(a1), f2 = unpack2(a2v), f3 = unpack2(a3);
        float dot = ((f0.x + f0.y) + (f1.x + f1.y)) + ((f2.x + f2.y) + (f3.x + f3.y));
        Prow[s] = dot;
        mx = fmaxf(mx, dot);
    }
    float sum = 0.f;
    for (int s = 0; s < SS; s++) {
        float e = __expf(0.125f * (Prow[s] - mx));
        Prow[s] = e;
        sum += e;
    }
    float inv = 1.f / sum;

    __syncthreads();
    for (int i = t * 4; i < TT * DHH; i += 128 * 4)
        *(float4*)&KV[i] = *(const float4*)&Vp[i];
    __syncthreads();

    ull o2[32];
#pragma unroll
    for (int i = 0; i < 32; i++) o2[i] = 0ull;
    for (int s = 0; s < SS; s++) {
        ull p2 = splat2(Prow[s]);
        const ulonglong2* vp2 = (const ulonglong2*)(KV + s * DHH);
#pragma unroll
        for (int i = 0; i < 16; i++) {
            ulonglong2 vv = vp2[i];
            o2[2 * i]     = ffma2(p2, vv.x, o2[2 * i]);
            o2[2 * i + 1] = ffma2(p2, vv.y, o2[2 * i + 1]);
        }
    }

    const int b = bh / HH, h = bh % HH;
    float* op = outp + ((size_t)b * TT + t) * CC + h * DHH;
#pragma unroll
    for (int j = 0; j < 32; j++) {
        float2 f = unpack2(o2[j]);
        op[2 * j]     = f.x * inv;
        op[2 * j + 1] = f.y * inv;
    }
}

// =============================================================================
// Two-pass joint (T,C) LayerNorm.  Pass 1: partial sums, grid (B, 8).
// Pass 2: normalize + write fp32 + bf16 hi/lo split, grid (B, 8).
// =============================================================================
__global__ __launch_bounds__(256) void ln_part1(
    const float* __restrict__ a, const float* __restrict__ r, float* __restrict__ red)
{
    const int b = blockIdx.x, ch = blockIdx.y;
    const size_t base = (size_t)b * (TT * CC) + (size_t)ch * 8192;
    const float4* pa = (const float4*)(a + base);
    const float4* pr = r ? (const float4*)(r + base) : nullptr;

    float s = 0.f, ss = 0.f;
    for (int i = threadIdx.x; i < 2048; i += 256) {
        float4 v = pa[i];
        if (pr) { float4 w = pr[i]; v.x += w.x; v.y += w.y; v.z += w.z; v.w += w.w; }
        s += (v.x + v.y) + (v.z + v.w);
        ss += (v.x * v.x + v.y * v.y) + (v.z * v.z + v.w * v.w);
    }
#pragma unroll
    for (int o = 16; o > 0; o >>= 1) {
        s += __shfl_down_sync(0xffffffffu, s, o);
        ss += __shfl_down_sync(0xffffffffu, ss, o);
    }
    __shared__ float rs[8], rss[8];
    const int w = threadIdx.x >> 5;
    if ((threadIdx.x & 31) == 0) { rs[w] = s; rss[w] = ss; }
    __syncthreads();
    if (threadIdx.x == 0) {
        float S = 0.f, SS2 = 0.f;
        for (int i = 0; i < 8; i++) { S += rs[i]; SS2 += rss[i]; }
        red[(b * 8 + ch) * 2 + 0] = S;
        red[(b * 8 + ch) * 2 + 1] = SS2;
    }
}

__global__ __launch_bounds__(256) void ln_part2(
    const float* __restrict__ a, const float* __restrict__ r,
    float* __restrict__ outp, bf16* __restrict__ ohi, bf16* __restrict__ olo,
    const float* __restrict__ red)
{
    const int b = blockIdx.x, ch = blockIdx.y;
    float S = 0.f, SS2 = 0.f;
#pragma unroll
    for (int i = 0; i < 8; i++) {
        S += red[(b * 8 + i) * 2 + 0];
        SS2 += red[(b * 8 + i) * 2 + 1];
    }
    const float N = (float)(TT * CC);
    const float mu = S / N;
    const float rsig = rsqrtf(SS2 / N - mu * mu + LN_EPS);

    const size_t base = (size_t)b * (TT * CC) + (size_t)ch * 8192;
    const float4* pa = (const float4*)(a + base);
    const float4* pr = r ? (const float4*)(r + base) : nullptr;
    float4* po = (float4*)(outp + base);
    for (int i = threadIdx.x; i < 2048; i += 256) {
        float4 v = pa[i];
        if (pr) { float4 w = pr[i]; v.x += w.x; v.y += w.y; v.z += w.z; v.w += w.w; }
        v.x = (v.x - mu) * rsig;
        v.y = (v.y - mu) * rsig;
        v.z = (v.z - mu) * rsig;
        v.w = (v.w - mu) * rsig;
        po[i] = v;
        uint32_t h0, l0, h1, l1, h2, l2, h3, l3;
        split1(v.x, h0, l0); split1(v.y, h1, l1);
        split1(v.z, h2, l2); split1(v.w, h3, l3);
        uint2 uh = make_uint2(h0 | (h1 << 16), h2 | (h3 << 16));
        uint2 ul = make_uint2(l0 | (l1 << 16), l2 | (l3 << 16));
        *(uint2*)(ohi + base + (size_t)i * 4) = uh;
        *(uint2*)(olo + base + (size_t)i * 4) = ul;
    }
}

// =============================================================================
extern "C" void kernel_launch(void* const* d_in, const int* in_sizes, int n_in,
                              void* d_out, int out_size)
{
    (void)in_sizes; (void)n_in; (void)out_size;

    const float* x_in  = (const float*)d_in[0];
    const float* enc   = (const float*)d_in[1];
    const float* sa_wq = (const float*)d_in[2];
    const float* sa_bq = (const float*)d_in[3];
    const float* sa_wk = (const float*)d_in[4];
    const float* sa_bk = (const float*)d_in[5];
    const float* sa_wv = (const float*)d_in[6];
    const float* sa_bv = (const float*)d_in[7];
    const float* ca_wq = (const float*)d_in[8];
    const float* ca_bq = (const float*)d_in[9];
    const float* ca_wk = (const float*)d_in[10];
    const float* ca_bk = (const float*)d_in[11];
    const float* ca_wv = (const float*)d_in[12];
    const float* ca_bv = (const float*)d_in[13];
    const float* ff_w1 = (const float*)d_in[14];
    const float* ff_b1 = (const float*)d_in[15];
    const float* ff_w2 = (const float*)d_in[16];
    const float* ff_b2 = (const float*)d_in[17];

    float *gx, *gq, *gk, *gv, *gatt, *gb, *gred;
    bf16 *gxhi, *gxlo, *gehi, *gelo, *ghhi, *ghlo, *gwhi, *gwlo;
    cudaGetSymbolAddress((void**)&gx, g_x);
    cudaGetSymbolAddress((void**)&gq, g_q);
    cudaGetSymbolAddress((void**)&gk, g_k);
    cudaGetSymbolAddress((void**)&gv, g_v);
    cudaGetSymbolAddress((void**)&gatt, g_att);
    cudaGetSymbolAddress((void**)&gxhi, g_xhi);
    cudaGetSymbolAddress((void**)&gxlo, g_xlo);
    cudaGetSymbolAddress((void**)&gehi, g_ehi);
    cudaGetSymbolAddress((void**)&gelo, g_elo);
    cudaGetSymbolAddress((void**)&ghhi, g_hhi);
    cudaGetSymbolAddress((void**)&ghlo, g_hlo);
    cudaGetSymbolAddress((void**)&gwhi, g_whi);
    cudaGetSymbolAddress((void**)&gwlo, g_wlo);
    cudaGetSymbolAddress((void**)&gb, g_bias);
    cudaGetSymbolAddress((void**)&gred, g_red);

    const int attn_smem = (TT * DHH + TT * 129) * (int)sizeof(float);
    cudaFuncSetAttribute(attn_kernel, cudaFuncAttributeMaxDynamicSharedMemorySize, attn_smem);
    cudaFuncSetAttribute(gemm_mma, cudaFuncAttributeMaxDynamicSharedMemorySize, GEMM_SMEM);

    cudaMemcpyAsync(gx, x_in, sizeof(float) * BB * TT * CC, cudaMemcpyDeviceToDevice);
    conv_split<<<296, 256>>>(x_in, gxhi, gxlo, BB * TT * CC / 8);
    conv_split<<<296, 256>>>(enc, gehi, gelo, BB * SS * CC / 8);

    for (int l = 0; l < LL; l++) {
        const size_t woff = (size_t)l * HH * CC * DHH;
        const size_t boff = (size_t)l * HH * DHH;

        // ---- self attention ----
        prep_qkv<<<dim3(8, 24), 256>>>(sa_wq + woff, sa_wk + woff, sa_wv + woff,
                                       sa_bq + boff, sa_bk + boff, sa_bv + boff,
                                       gwhi, gwlo, gb);
        gemm_mma<<<dim3(64, 12), 256, GEMM_SMEM>>>(
            gxhi, gxlo, gxhi, gxlo, CC, gwhi, gwlo, gb, nullptr,
            nullptr, nullptr, nullptr, 0, gq, gk, gv, 0, 1);
        attn_kernel<<<BB * HH, 128, attn_smem>>>(gq, gk, gv, gatt);
        ln_part1<<<dim3(BB, 8), 256>>>(gx, gatt, gred);
        ln_part2<<<dim3(BB, 8), 256>>>(gx, gatt, gx, gxhi, gxlo, gred);

        // ---- cross attention ----
        prep_qkv<<<dim3(8, 24), 256>>>(ca_wq + woff, ca_wk + woff, ca_wv + woff,
                                       ca_bq + boff, ca_bk + boff, ca_bv + boff,
                                       gwhi, gwlo, gb);
        gemm_mma<<<dim3(64, 12), 256, GEMM_SMEM>>>(
            gxhi, gxlo, gehi, gelo, CC, gwhi, gwlo, gb, nullptr,
            nullptr, nullptr, nullptr, 0, gq, gk, gv, 0, 1);
        attn_kernel<<<BB * HH, 128, attn_smem>>>(gq, gk, gv, gatt);
        ln_part1<<<dim3(BB, 8), 256>>>(gx, gatt, gred);
        ln_part2<<<dim3(BB, 8), 256>>>(gx, gatt, gx, gxhi, gxlo, gred);

        // ---- feed forward ----
        prep_plain<<<dim3(8, 32), 256>>>(ff_w1 + (size_t)l * CC * FFF, CC, FFF, gwhi, gwlo);
        gemm_mma<<<dim3(64, 16), 256, GEMM_SMEM>>>(
            gxhi, gxlo, gxhi, gxlo, CC, gwhi, gwlo, ff_b1 + (size_t)l * FFF, nullptr,
            nullptr, ghhi, ghlo, FFF, nullptr, nullptr, nullptr, 1, 2);
        prep_plain<<<dim3(32, 8), 256>>>(ff_w2 + (size_t)l * FFF * CC, FFF, CC, gwhi, gwlo);
        gemm_mma<<<dim3(64, 4), 256, GEMM_SMEM>>>(
            ghhi, ghlo, ghhi, ghlo, FFF, gwhi, gwlo, ff_b2 + (size_t)l * CC, gx,
            gatt, nullptr, nullptr, CC, nullptr, nullptr, nullptr, 0, 0);
        ln_part1<<<dim3(BB, 8), 256>>>(gatt, nullptr, gred);
        ln_part2<<<dim3(BB, 8), 256>>>(gatt, nullptr, gx, gxhi, gxlo, gred);
    }

    cudaMemcpyAsync(d_out, gx, sizeof(float) * BB * TT * CC, cudaMemcpyDeviceToDevice);
}

// round 14
// speedup vs baseline: 1.2155x; 1.2155x over previous
#include <cuda_runtime.h>
#include <cuda_bf16.h>
#include <cstdint>

// Problem dims
#define BB 64
#define TT 128
#define SS 128
#define CC 512
#define HH 8
#define DHH 64
#define FFF 2048
#define LL 6
#define LN_EPS 1e-5f

typedef unsigned long long ull;
typedef __nv_bfloat16 bf16;

// ---------------- scratch (static device allocations — allowed) --------------
__device__ float g_x[BB * TT * CC];
__device__ float g_q[BB * HH * TT * DHH];
__device__ float g_k[BB * HH * TT * DHH];
__device__ float g_v[BB * HH * TT * DHH];
__device__ float g_att[BB * TT * CC];
__device__ bf16 g_xhi[BB * TT * CC];          // split activations (decoder x)
__device__ bf16 g_xlo[BB * TT * CC];
__device__ bf16 g_ehi[BB * SS * CC];          // split encoder output
__device__ bf16 g_elo[BB * SS * CC];
__device__ bf16 g_hhi[BB * TT * FFF];         // split ff hidden
__device__ bf16 g_hlo[BB * TT * FFF];
__device__ bf16 g_whi[2048 * 512];            // prepped weights (max N*K = 1M)
__device__ bf16 g_wlo[2048 * 512];
__device__ float g_bias[2048];
__device__ float g_red[BB * 8 * 2];           // LN partial sums

// ---------------- packed f32x2 helpers ---------------------------------------
__device__ __forceinline__ ull ffma2(ull a, ull b, ull c) {
    ull d; asm("fma.rn.f32x2 %0, %1, %2, %3;" : "=l"(d) : "l"(a), "l"(b), "l"(c));
    return d;
}
__device__ __forceinline__ ull splat2(float x) {
    ull d; asm("mov.b64 %0, {%1, %1};" : "=l"(d) : "f"(x)); return d;
}
__device__ __forceinline__ float2 unpack2(ull v) {
    float2 r; asm("mov.b64 {%0, %1}, %2;" : "=f"(r.x), "=f"(r.y) : "l"(v)); return r;
}
__device__ __forceinline__ uint32_t smem_u32(const void* p) {
    uint32_t a;
    asm("{ .reg .u64 t; cvta.to.shared.u64 t, %1; cvt.u32.u64 %0, t; }" : "=r"(a) : "l"(p));
    return a;
}
__device__ __forceinline__ uint32_t bfu(bf16 v) {
    return (uint32_t)__bfloat16_as_ushort(v);
}
// split one fp32 -> hi/lo bf16 pair
__device__ __forceinline__ void split1(float x, uint32_t& hi, uint32_t& lo) {
    bf16 h = __float2bfloat16_rn(x);
    hi = bfu(h);
    lo = bfu(__float2bfloat16_rn(x - __bfloat162float(h)));
}

// ---------------- mma.sync / ldmatrix / cp.async (plain-sm_103 PTX) ----------
#define LDX4(r0, r1, r2, r3, addr) \
    asm volatile("ldmatrix.sync.aligned.m8n8.x4.shared.b16 {%0,%1,%2,%3}, [%4];" \
                 : "=r"(r0), "=r"(r1), "=r"(r2), "=r"(r3) : "r"(addr))

__device__ __forceinline__ void mma16816(float* c, const uint32_t* a, const uint32_t* b) {
    asm volatile(
        "mma.sync.aligned.m16n8k16.row.col.f32.bf16.bf16.f32 "
        "{%0,%1,%2,%3}, {%4,%5,%6,%7}, {%8,%9}, {%0,%1,%2,%3};"
        : "+f"(c[0]), "+f"(c[1]), "+f"(c[2]), "+f"(c[3])
        : "r"(a[0]), "r"(a[1]), "r"(a[2]), "r"(a[3]), "r"(b[0]), "r"(b[1]));
}
__device__ __forceinline__ void cpasync16(uint32_t dst, const void* src) {
    asm volatile("cp.async.cg.shared.global [%0], [%1], 16;" :: "r"(dst), "l"(src));
}

// =============================================================================
// HMMA split-bf16 GEMM, cp.async 3-stage pipelined, 2 CTAs/SM.
// CTA tile 128x128, BK=32, 8 warps (2x4), warp tile 64x32, 3-term compensation.
// smem rows PACK hi+lo: [32 hi halves | 32 lo halves | 16B pad] = 144B stride
// (16B-aligned; 8 rows*144 mod 128 = {0,16,..,112} all distinct banks).
// Stage = A-pack + B-pack = 2*18432 = 36864B; 3 stages = 110592B -> 2 CTAs/SM.
// ONE __syncthreads per K-chunk; loads run 2 chunks ahead.
// COALESCED loads: v = p*256+tid, row = v>>3, sub = v&7; sub 0-3 -> hi 64B of
// row (contiguous per 4-thread group), sub 4-7 -> lo 64B (contiguous).
// mode: 0 = fp32 out (+res,+relu)   1 = qkv scatter   2 = bf16 hi/lo out (+relu)
// =============================================================================
#define AR_STRIDE 144
#define MAT_BYTES (128 * AR_STRIDE)           // 18432 (one packed matrix)
#define STAGE_BYTES (2 * MAT_BYTES)           // 36864
#define GEMM_SMEM (3 * STAGE_BYTES)           // 110592 -> 2 CTAs/SM

__global__ __launch_bounds__(256, 2) void gemm_mma(
    const bf16* __restrict__ Aq_hi, const bf16* __restrict__ Aq_lo,
    const bf16* __restrict__ Akv_hi, const bf16* __restrict__ Akv_lo, int Kdim,
    const bf16* __restrict__ Whi, const bf16* __restrict__ Wlo,
    const float* __restrict__ bias, const float* __restrict__ res,
    float* __restrict__ outp, bf16* __restrict__ ohi, bf16* __restrict__ olo, int ldo,
    float* __restrict__ Oq, float* __restrict__ Ok, float* __restrict__ Ov,
    int relu, int mode)
{
    extern __shared__ char sm[];
    const uint32_t smb = smem_u32(sm);
    const int tid = threadIdx.x;
    const int wid = tid >> 5, lane = tid & 31;
    const int mw = wid >> 2, nw = wid & 3;

    const int m0 = blockIdx.x * 128;
    const int n0 = blockIdx.y * 128;
    const bf16 *Ahp, *Alp;
    if (mode == 1 && n0 >= 512) { Ahp = Akv_hi; Alp = Akv_lo; }
    else                        { Ahp = Aq_hi;  Alp = Aq_lo; }

    // coalesced load slots: row = tid>>3 (+32 per pass), sub = tid&7
    // sub 0-3: hi array, 16B chunk sub;  sub 4-7: lo array, 16B chunk sub-4.
    const int lrow = tid >> 3, lsub = tid & 7;
    const int lhalf = lsub >> 2;              // 0 = hi, 1 = lo
    const int lchunk = lsub & 3;              // 16B chunk within 64B half
    const bf16* pA = (lhalf ? Alp : Ahp) + (size_t)(m0 + lrow) * Kdim + lchunk * 8;
    const bf16* pB = (lhalf ? Wlo : Whi) + (size_t)(n0 + lrow) * Kdim + lchunk * 8;
    const uint32_t soRow = lrow * AR_STRIDE + lhalf * 64 + lchunk * 16;
    const size_t gstep = (size_t)32 * Kdim;   // 32 rows per pass

    float acc[4][4][4];
#pragma unroll
    for (int i = 0; i < 4; i++)
#pragma unroll
        for (int j = 0; j < 4; j++)
#pragma unroll
            for (int r = 0; r < 4; r++) acc[i][j][r] = 0.f;

    // ldmatrix per-lane offsets (relative to stage base); hi at +0, lo at +64
    const int aoff = (mw * 64 + (lane & 15)) * AR_STRIDE + (lane >> 4) * 16;
    const int mi = lane >> 3;
    const int n_off = ((mi >> 1) * 8) + (lane & 7);
    const int k_off = (mi & 1) * 8;
    const int boff = (nw * 32 + n_off) * AR_STRIDE + k_off * 2;

    const int nch = Kdim >> 5;

#define LOAD_STAGE(slotb, kc) do {                                             \
        _Pragma("unroll")                                                      \
        for (int p = 0; p < 4; p++) {                                          \
            cpasync16((slotb) + soRow + p * 32 * AR_STRIDE,                    \
                      pA + (kc) + p * gstep);                                  \
            cpasync16((slotb) + MAT_BYTES + soRow + p * 32 * AR_STRIDE,        \
                      pB + (kc) + p * gstep);                                  \
        }                                                                      \
        asm volatile("cp.async.commit_group;");                                \
    } while (0)

    LOAD_STAGE(smb, 0);
    LOAD_STAGE(smb + STAGE_BYTES, 32);

    int cs = 0, ls = 2;
    for (int c = 0; c < nch; c++) {
        if (c + 1 < nch) asm volatile("cp.async.wait_group 1;");
        else             asm volatile("cp.async.wait_group 0;");
        __syncthreads();
        if (c + 2 < nch) {
            LOAD_STAGE(smb + ls * STAGE_BYTES, (c + 2) << 5);
            ls = (ls == 2) ? 0 : ls + 1;
        }

        const uint32_t sb = smb + cs * STAGE_BYTES;
        cs = (cs == 2) ? 0 : cs + 1;
        const uint32_t sA = sb, sB = sb + MAT_BYTES;

#pragma unroll
        for (int kk = 0; kk < 2; kk++) {
            uint32_t bh[4][2], bl[4][2];
            LDX4(bh[0][0], bh[0][1], bh[1][0], bh[1][1], sB + boff + kk * 32);
            LDX4(bh[2][0], bh[2][1], bh[3][0], bh[3][1], sB + boff + 16 * AR_STRIDE + kk * 32);
            LDX4(bl[0][0], bl[0][1], bl[1][0], bl[1][1], sB + boff + 64 + kk * 32);
            LDX4(bl[2][0], bl[2][1], bl[3][0], bl[3][1], sB + boff + 16 * AR_STRIDE + 64 + kk * 32);
#pragma unroll
            for (int i = 0; i < 4; i++) {
                uint32_t ah[4], al[4];
                LDX4(ah[0], ah[1], ah[2], ah[3], sA + aoff + i * 16 * AR_STRIDE + kk * 32);
                LDX4(al[0], al[1], al[2], al[3], sA + aoff + i * 16 * AR_STRIDE + 64 + kk * 32);
#pragma unroll
                for (int j = 0; j < 4; j++) {
                    mma16816(acc[i][j], ah, bh[j]);
                    mma16816(acc[i][j], ah, bl[j]);
                    mma16816(acc[i][j], al, bh[j]);
                }
            }
        }
    }
#undef LOAD_STAGE

    // ---- epilogue ----
    const int gid = lane >> 2, tg = lane & 3;
#pragma unroll
    for (int i = 0; i < 4; i++) {
#pragma unroll
        for (int j = 0; j < 4; j++) {
            int row0 = m0 + mw * 64 + i * 16 + gid;
            int row1 = row0 + 8;
            int col = n0 + nw * 32 + j * 8 + tg * 2;
            float b0v = bias[col], b1v = bias[col + 1];
            float v00 = acc[i][j][0] + b0v, v01 = acc[i][j][1] + b1v;
            float v10 = acc[i][j][2] + b0v, v11 = acc[i][j][3] + b1v;
            if (mode == 0) {
                if (res) {
                    float2 r0 = *(const float2*)(res + (size_t)row0 * ldo + col);
                    float2 r1 = *(const float2*)(res + (size_t)row1 * ldo + col);
                    v00 += r0.x; v01 += r0.y; v10 += r1.x; v11 += r1.y;
                }
                if (relu) {
                    v00 = fmaxf(v00, 0.f); v01 = fmaxf(v01, 0.f);
                    v10 = fmaxf(v10, 0.f); v11 = fmaxf(v11, 0.f);
                }
                *(float2*)(outp + (size_t)row0 * ldo + col) = make_float2(v00, v01);
                *(float2*)(outp + (size_t)row1 * ldo + col) = make_float2(v10, v11);
            } else if (mode == 1) {
                const int z = col >> 9, hh = (col >> 6) & 7, d0 = col & 63;
                float* O = (z == 0) ? Oq : (z == 1 ? Ok : Ov);
                int b0i = row0 >> 7, t0 = row0 & 127;
                int b1i = row1 >> 7, t1 = row1 & 127;
                *(float2*)(O + (((size_t)(b0i * HH + hh)) * TT + t0) * DHH + d0) = make_float2(v00, v01);
                *(float2*)(O + (((size_t)(b1i * HH + hh)) * TT + t1) * DHH + d0) = make_float2(v10, v11);
            } else {
                if (relu) {
                    v00 = fmaxf(v00, 0.f); v01 = fmaxf(v01, 0.f);
                    v10 = fmaxf(v10, 0.f); v11 = fmaxf(v11, 0.f);
                }
                uint32_t h00, l00, h01, l01, h10, l10, h11, l11;
                split1(v00, h00, l00); split1(v01, h01, l01);
                split1(v10, h10, l10); split1(v11, h11, l11);
                *(uint32_t*)(ohi + (size_t)row0 * ldo + col) = h00 | (h01 << 16);
                *(uint32_t*)(olo + (size_t)row0 * ldo + col) = l00 | (l01 << 16);
                *(uint32_t*)(ohi + (size_t)row1 * ldo + col) = h10 | (h11 << 16);
                *(uint32_t*)(olo + (size_t)row1 * ldo + col) = l10 | (l11 << 16);
            }
        }
    }
}

// =============================================================================
// Weight prep: transpose fp32 weights into K-major bf16 hi/lo [N,K]
// =============================================================================
__global__ __launch_bounds__(256) void prep_qkv(
    const float* __restrict__ wq, const float* __restrict__ wk, const float* __restrict__ wv,
    const float* __restrict__ bq, const float* __restrict__ bk, const float* __restrict__ bv,
    bf16* __restrict__ whi, bf16* __restrict__ wlo, float* __restrict__ gb)
{
    __shared__ float smt[64][65];
    const int tid = threadIdx.x;
    const int c0 = blockIdx.x * 64;
    const int nb0 = blockIdx.y * 64;
    const int z = nb0 >> 9, hh = (nb0 >> 6) & 7;
    const float* W = ((z == 0) ? wq : (z == 1 ? wk : wv)) + (size_t)hh * CC * DHH;

#pragma unroll
    for (int p = 0; p < 4; p++) {
        int v = p * 256 + tid;
        int ci = v >> 4, q = v & 15;
        float4 a = *(const float4*)(W + (size_t)(c0 + ci) * DHH + q * 4);
        smt[ci][q * 4 + 0] = a.x; smt[ci][q * 4 + 1] = a.y;
        smt[ci][q * 4 + 2] = a.z; smt[ci][q * 4 + 3] = a.w;
    }
    __syncthreads();
#pragma unroll
    for (int p = 0; p < 2; p++) {
        int u = p * 256 + tid;
        int d = u >> 3, cv = u & 7;
        uint4 uh, ul;
        uint32_t* ph = (uint32_t*)&uh;
        uint32_t* pl = (uint32_t*)&ul;
#pragma unroll
        for (int j = 0; j < 4; j++) {
            uint32_t h0, l0, h1, l1;
            split1(smt[cv * 8 + 2 * j][d], h0, l0);
            split1(smt[cv * 8 + 2 * j + 1][d], h1, l1);
            ph[j] = h0 | (h1 << 16);
            pl[j] = l0 | (l1 << 16);
        }
        size_t o = (size_t)(nb0 + d) * CC + c0 + cv * 8;
        *(uint4*)(whi + o) = uh;
        *(uint4*)(wlo + o) = ul;
    }
    if (blockIdx.x == 0 && tid < 64) {
        const float* bsrc = (z == 0) ? bq : (z == 1 ? bk : bv);
        gb[nb0 + tid] = bsrc[hh * DHH + tid];
    }
}

__global__ __launch_bounds__(256) void prep_plain(
    const float* __restrict__ W, int Kd, int Nd,
    bf16* __restrict__ whi, bf16* __restrict__ wlo)
{
    __shared__ float smt[64][65];
    const int tid = threadIdx.x;
    const int c0 = blockIdx.x * 64;
    const int nb0 = blockIdx.y * 64;

#pragma unroll
    for (int p = 0; p < 4; p++) {
        int v = p * 256 + tid;
        int ci = v >> 4, q = v & 15;
        float4 a = *(const float4*)(W + (size_t)(c0 + ci) * Nd + nb0 + q * 4);
        smt[ci][q * 4 + 0] = a.x; smt[ci][q * 4 + 1] = a.y;
        smt[ci][q * 4 + 2] = a.z; smt[ci][q * 4 + 3] = a.w;
    }
    __syncthreads();
#pragma unroll
    for (int p = 0; p < 2; p++) {
        int u = p * 256 + tid;
        int d = u >> 3, cv = u & 7;
        uint4 uh, ul;
        uint32_t* ph = (uint32_t*)&uh;
        uint32_t* pl = (uint32_t*)&ul;
#pragma unroll
        for (int j = 0; j < 4; j++) {
            uint32_t h0, l0, h1, l1;
            split1(smt[cv * 8 + 2 * j][d], h0, l0);
            split1(smt[cv * 8 + 2 * j + 1][d], h1, l1);
            ph[j] = h0 | (h1 << 16);
            pl[j] = l0 | (l1 << 16);
        }
        size_t o = (size_t)(nb0 + d) * Kd + c0 + cv * 8;
        *(uint4*)(whi + o) = uh;
        *(uint4*)(wlo + o) = ul;
    }
}

// ---- standalone fp32 -> bf16 hi/lo split (for x_in and encoder_output) ------
__global__ __launch_bounds__(256) void conv_split(
    const float* __restrict__ a, bf16* __restrict__ hi, bf16* __restrict__ lo, int n8)
{
    for (int i = blockIdx.x * 256 + threadIdx.x; i < n8; i += gridDim.x * 256) {
        float4 v0 = *(const float4*)(a + (size_t)i * 8);
        float4 v1 = *(const float4*)(a + (size_t)i * 8 + 4);
        uint4 uh, ul;
        uint32_t* ph = (uint32_t*)&uh;
        uint32_t* pl = (uint32_t*)&ul;
#pragma unroll
        for (int j = 0; j < 4; j++) {
            float x0 = (j < 2) ? ((const float*)&v0)[2 * j] : ((const float*)&v1)[2 * (j - 2)];
            float x1 = (j < 2) ? ((const float*)&v0)[2 * j + 1] : ((const float*)&v1)[2 * (j - 2) + 1];
            uint32_t h0, l0v, h1, l1v;
            split1(x0, h0, l0v); split1(x1, h1, l1v);
            ph[j] = h0 | (h1 << 16);
            pl[j] = l0v | (l1v << 16);
        }
        *(uint4*)(hi + (size_t)i * 8) = uh;
        *(uint4*)(lo + (size_t)i * 8) = ul;
    }
}

// =============================================================================
// Attention: one CTA per (b,h). 128 threads, thread t owns query row t.
// =============================================================================
__global__ __launch_bounds__(128) void attn_kernel(
    const float* __restrict__ Q, const float* __restrict__ K,
    const float* __restrict__ V, float* __restrict__ outp)
{
    extern __shared__ float smf[];
    float* KV = smf;
    float* P = smf + TT * DHH;

    const int bh = blockIdx.x;
    const int t = threadIdx.x;
    const size_t base = (size_t)bh * TT * DHH;
    const float* Qp = Q + base;
    const float* Kp = K + base;
    const float* Vp = V + base;

    for (int i = t * 4; i < TT * DHH; i += 128 * 4)
        *(float4*)&KV[i] = *(const float4*)&Kp[i];

    ulonglong2 q2[16];
    const ulonglong2* qsrc = (const ulonglong2*)(Qp + (size_t)t * DHH);
#pragma unroll
    for (int i = 0; i < 16; i++) q2[i] = qsrc[i];
    __syncthreads();

    float* Prow = P + t * 129;
    float mx = -1e30f;
    for (int s = 0; s < SS; s++) {
        const ulonglong2* kp2 = (const ulonglong2*)(KV + s * DHH);
        ull a0 = 0, a1 = 0, a2v = 0, a3 = 0;
#pragma unroll
        for (int i = 0; i < 16; i += 2) {
            ulonglong2 kv0 = kp2[i], kv1 = kp2[i + 1];
            a0 = ffma2(q2[i].x, kv0.x, a0);
            a1 = ffma2(q2[i].y, kv0.y, a1);
            a2v = ffma2(q2[i + 1].x, kv1.x, a2v);
            a3 = ffma2(q2[i + 1].y, kv1.y, a3);
        }
        float2 f0 = unpack2(a0), f1 = unpack2(a1), f2 = unpack2(a2v), f3 = unpack2(a3);
        float dot = ((f0.x + f0.y) + (f1.x + f1.y)) + ((f2.x + f2.y) + (f3.x + f3.y));
        Prow[s] = dot;
        mx = fmaxf(mx, dot);
    }
    float sum = 0.f;
    for (int s = 0; s < SS; s++) {
        float e = __expf(0.125f * (Prow[s] - mx));
        Prow[s] = e;
        sum += e;
    }
    float inv = 1.f / sum;

    __syncthreads();
    for (int i = t * 4; i < TT * DHH; i += 128 * 4)
        *(float4*)&KV[i] = *(const float4*)&Vp[i];
    __syncthreads();

    ull o2[32];
#pragma unroll
    for (int i = 0; i < 32; i++) o2[i] = 0ull;
    for (int s = 0; s < SS; s++) {
        ull p2 = splat2(Prow[s]);
        const ulonglong2* vp2 = (const ulonglong2*)(KV + s * DHH);
#pragma unroll
        for (int i = 0; i < 16; i++) {
            ulonglong2 vv = vp2[i];
            o2[2 * i]     = ffma2(p2, vv.x, o2[2 * i]);
            o2[2 * i + 1] = ffma2(p2, vv.y, o2[2 * i + 1]);
        }
    }

    const int b = bh / HH, h = bh % HH;
    float* op = outp + ((size_t)b * TT + t) * CC + h * DHH;
#pragma unroll
    for (int j = 0; j < 32; j++) {
        float2 f = unpack2(o2[j]);
        op[2 * j]     = f.x * inv;
        op[2 * j + 1] = f.y * inv;
    }
}

// =============================================================================
// Two-pass joint (T,C) LayerNorm.  Pass 1: partial sums, grid (B, 8).
// Pass 2: normalize + write fp32 + bf16 hi/lo split, grid (B, 8).
// =============================================================================
__global__ __launch_bounds__(256) void ln_part1(
    const float* __restrict__ a, const float* __restrict__ r, float* __restrict__ red)
{
    const int b = blockIdx.x, ch = blockIdx.y;
    const size_t base = (size_t)b * (TT * CC) + (size_t)ch * 8192;
    const float4* pa = (const float4*)(a + base);
    const float4* pr = r ? (const float4*)(r + base) : nullptr;

    float s = 0.f, ss = 0.f;
    for (int i = threadIdx.x; i < 2048; i += 256) {
        float4 v = pa[i];
        if (pr) { float4 w = pr[i]; v.x += w.x; v.y += w.y; v.z += w.z; v.w += w.w; }
        s += (v.x + v.y) + (v.z + v.w);
        ss += (v.x * v.x + v.y * v.y) + (v.z * v.z + v.w * v.w);
    }
#pragma unroll
    for (int o = 16; o > 0; o >>= 1) {
        s += __shfl_down_sync(0xffffffffu, s, o);
        ss += __shfl_down_sync(0xffffffffu, ss, o);
    }
    __shared__ float rs[8], rss[8];
    const int w = threadIdx.x >> 5;
    if ((threadIdx.x & 31) == 0) { rs[w] = s; rss[w] = ss; }
    __syncthreads();
    if (threadIdx.x == 0) {
        float S = 0.f, SS2 = 0.f;
        for (int i = 0; i < 8; i++) { S += rs[i]; SS2 += rss[i]; }
        red[(b * 8 + ch) * 2 + 0] = S;
        red[(b * 8 + ch) * 2 + 1] = SS2;
    }
}

__global__ __launch_bounds__(256) void ln_part2(
    const float* __restrict__ a, const float* __restrict__ r,
    float* __restrict__ outp, bf16* __restrict__ ohi, bf16* __restrict__ olo,
    const float* __restrict__ red)
{
    const int b = blockIdx.x, ch = blockIdx.y;
    float S = 0.f, SS2 = 0.f;
#pragma unroll
    for (int i = 0; i < 8; i++) {
        S += red[(b * 8 + i) * 2 + 0];
        SS2 += red[(b * 8 + i) * 2 + 1];
    }
    const float N = (float)(TT * CC);
    const float mu = S / N;
    const float rsig = rsqrtf(SS2 / N - mu * mu + LN_EPS);

    const size_t base = (size_t)b * (TT * CC) + (size_t)ch * 8192;
    const float4* pa = (const float4*)(a + base);
    const float4* pr = r ? (const float4*)(r + base) : nullptr;
    float4* po = (float4*)(outp + base);
    for (int i = threadIdx.x; i < 2048; i += 256) {
        float4 v = pa[i];
        if (pr) { float4 w = pr[i]; v.x += w.x; v.y += w.y; v.z += w.z; v.w += w.w; }
        v.x = (v.x - mu) * rsig;
        v.y = (v.y - mu) * rsig;
        v.z = (v.z - mu) * rsig;
        v.w = (v.w - mu) * rsig;
        po[i] = v;
        uint32_t h0, l0, h1, l1, h2, l2, h3, l3;
        split1(v.x, h0, l0); split1(v.y, h1, l1);
        split1(v.z, h2, l2); split1(v.w, h3, l3);
        uint2 uh = make_uint2(h0 | (h1 << 16), h2 | (h3 << 16));
        uint2 ul = make_uint2(l0 | (l1 << 16), l2 | (l3 << 16));
        *(uint2*)(ohi + base + (size_t)i * 4) = uh;
        *(uint2*)(olo + base + (size_t)i * 4) = ul;
    }
}

// =============================================================================
extern "C" void kernel_launch(void* const* d_in, const int* in_sizes, int n_in,
                              void* d_out, int out_size)
{
    (void)in_sizes; (void)n_in; (void)out_size;

    const float* x_in  = (const float*)d_in[0];
    const float* enc   = (const float*)d_in[1];
    const float* sa_wq = (const float*)d_in[2];
    const float* sa_bq = (const float*)d_in[3];
    const float* sa_wk = (const float*)d_in[4];
    const float* sa_bk = (const float*)d_in[5];
    const float* sa_wv = (const float*)d_in[6];
    const float* sa_bv = (const float*)d_in[7];
    const float* ca_wq = (const float*)d_in[8];
    const float* ca_bq = (const float*)d_in[9];
    const float* ca_wk = (const float*)d_in[10];
    const float* ca_bk = (const float*)d_in[11];
    const float* ca_wv = (const float*)d_in[12];
    const float* ca_bv = (const float*)d_in[13];
    const float* ff_w1 = (const float*)d_in[14];
    const float* ff_b1 = (const float*)d_in[15];
    const float* ff_w2 = (const float*)d_in[16];
    const float* ff_b2 = (const float*)d_in[17];

    float *gx, *gq, *gk, *gv, *gatt, *gb, *gred;
    bf16 *gxhi, *gxlo, *gehi, *gelo, *ghhi, *ghlo, *gwhi, *gwlo;
    cudaGetSymbolAddress((void**)&gx, g_x);
    cudaGetSymbolAddress((void**)&gq, g_q);
    cudaGetSymbolAddress((void**)&gk, g_k);
    cudaGetSymbolAddress((void**)&gv, g_v);
    cudaGetSymbolAddress((void**)&gatt, g_att);
    cudaGetSymbolAddress((void**)&gxhi, g_xhi);
    cudaGetSymbolAddress((void**)&gxlo, g_xlo);
    cudaGetSymbolAddress((void**)&gehi, g_ehi);
    cudaGetSymbolAddress((void**)&gelo, g_elo);
    cudaGetSymbolAddress((void**)&ghhi, g_hhi);
    cudaGetSymbolAddress((void**)&ghlo, g_hlo);
    cudaGetSymbolAddress((void**)&gwhi, g_whi);
    cudaGetSymbolAddress((void**)&gwlo, g_wlo);
    cudaGetSymbolAddress((void**)&gb, g_bias);
    cudaGetSymbolAddress((void**)&gred, g_red);

    const int attn_smem = (TT * DHH + TT * 129) * (int)sizeof(float);
    cudaFuncSetAttribute(attn_kernel, cudaFuncAttributeMaxDynamicSharedMemorySize, attn_smem);
    cudaFuncSetAttribute(gemm_mma, cudaFuncAttributeMaxDynamicSharedMemorySize, GEMM_SMEM);

    cudaMemcpyAsync(gx, x_in, sizeof(float) * BB * TT * CC, cudaMemcpyDeviceToDevice);
    conv_split<<<296, 256>>>(x_in, gxhi, gxlo, BB * TT * CC / 8);
    conv_split<<<296, 256>>>(enc, gehi, gelo, BB * SS * CC / 8);

    for (int l = 0; l < LL; l++) {
        const size_t woff = (size_t)l * HH * CC * DHH;
        const size_t boff = (size_t)l * HH * DHH;

        // ---- self attention ----
        prep_qkv<<<dim3(8, 24), 256>>>(sa_wq + woff, sa_wk + woff, sa_wv + woff,
                                       sa_bq + boff, sa_bk + boff, sa_bv + boff,
                                       gwhi, gwlo, gb);
        gemm_mma<<<dim3(64, 12), 256, GEMM_SMEM>>>(
            gxhi, gxlo, gxhi, gxlo, CC, gwhi, gwlo, gb, nullptr,
            nullptr, nullptr, nullptr, 0, gq, gk, gv, 0, 1);
        attn_kernel<<<BB * HH, 128, attn_smem>>>(gq, gk, gv, gatt);
        ln_part1<<<dim3(BB, 8), 256>>>(gx, gatt, gred);
        ln_part2<<<dim3(BB, 8), 256>>>(gx, gatt, gx, gxhi, gxlo, gred);

        // ---- cross attention ----
        prep_qkv<<<dim3(8, 24), 256>>>(ca_wq + woff, ca_wk + woff, ca_wv + woff,
                                       ca_bq + boff, ca_bk + boff, ca_bv + boff,
                                       gwhi, gwlo, gb);
        gemm_mma<<<dim3(64, 12), 256, GEMM_SMEM>>>(
            gxhi, gxlo, gehi, gelo, CC, gwhi, gwlo, gb, nullptr,
            nullptr, nullptr, nullptr, 0, gq, gk, gv, 0, 1);
        attn_kernel<<<BB * HH, 128, attn_smem>>>(gq, gk, gv, gatt);
        ln_part1<<<dim3(BB, 8), 256>>>(gx, gatt, gred);
        ln_part2<<<dim3(BB, 8), 256>>>(gx, gatt, gx, gxhi, gxlo, gred);

        // ---- feed forward ----
        prep_plain<<<dim3(8, 32), 256>>>(ff_w1 + (size_t)l * CC * FFF, CC, FFF, gwhi, gwlo);
        gemm_mma<<<dim3(64, 16), 256, GEMM_SMEM>>>(
            gxhi, gxlo, gxhi, gxlo, CC, gwhi, gwlo, ff_b1 + (size_t)l * FFF, nullptr,
            nullptr, ghhi, ghlo, FFF, nullptr, nullptr, nullptr, 1, 2);
        prep_plain<<<dim3(32, 8), 256>>>(ff_w2 + (size_t)l * FFF * CC, FFF, CC, gwhi, gwlo);
        gemm_mma<<<dim3(64, 4), 256, GEMM_SMEM>>>(
            ghhi, ghlo, ghhi, ghlo, FFF, gwhi, gwlo, ff_b2 + (size_t)l * CC, gx,
            gatt, nullptr, nullptr, CC, nullptr, nullptr, nullptr, 0, 0);
        ln_part1<<<dim3(BB, 8), 256>>>(gatt, nullptr, gred);
        ln_part2<<<dim3(BB, 8), 256>>>(gatt, nullptr, gx, gxhi, gxlo, gred);
    }

    cudaMemcpyAsync(d_out, gx, sizeof(float) * BB * TT * CC, cudaMemcpyDeviceToDevice);
}